// round 8
// baseline (speedup 1.0000x reference)
#include <cuda_runtime.h>

// ---------------------------------------------------------------------------
// Shapes: B=4, T=8192, D=1024, S=16 slots, H=8 heads, HD=128, segL=512
// ---------------------------------------------------------------------------
typedef unsigned long long ull;

#define OUT_ELEMS   33554432u   // 4*8192*1024
#define MEM_ELEMS   65536u      // 4*16*1024

// scratch offsets (floats)
#define OFF_NS     0u           // normed mem_slots        [16,1024]
#define OFF_Q      16384u       // q slots                 [16,1024]
#define OFF_A      32768u       // a[s][h][c]              [16,8,1024]
#define OFF_WWKT   163840u      // Wwk^T                   [1024,1024]
#define OFF_WRQT   1212416u     // Wrq^T                   [1024,1024]
#define OFF_SC     2260992u     // scores/weights          [64][8][512]
#define OFF_Y      2523136u     // y[seg][h][c]            [64,8,1024]
#define OFF_MEM0   3047424u     // mem after write_memory  [64,1024]
#define OFF_QKV    3112960u     // qkv                     [64,3072]
#define OFF_ATT    3309568u     // slot-attn out           [64,1024]
#define OFF_PROJ   3375104u     // proj pre-norm           [64,1024]
#define OFF_MEMN   3440640u     // normed memory           [64,1024]
#define OFF_KR     3506176u     // memory@Wrk              [64,1024]
#define OFF_VR     3571712u     // memory@Wrv              [64,1024]
#define OFF_KK     3637248u     // kr@Wrq^T                [64,1024]
#define SCRATCH_FLOATS 3702784u

__device__ __align__(16) float g_scratch[SCRATCH_FLOATS];

// ---- packed f32x2 helpers (Blackwell FFMA2) --------------------------------
__device__ __forceinline__ ull pk2(float x, float y) {
    ull r; asm("mov.b64 %0,{%1,%2};" : "=l"(r) : "f"(x), "f"(y)); return r;
}
__device__ __forceinline__ float2 upk2(ull v) {
    float2 f; asm("mov.b64 {%0,%1},%2;" : "=f"(f.x), "=f"(f.y) : "l"(v)); return f;
}
__device__ __forceinline__ void fma2(ull& d, ull a, ull b) {
    asm("fma.rn.f32x2 %0,%1,%2,%0;" : "+l"(d) : "l"(a), "l"(b));
}

// ---------------------------------------------------------------------------
// 1024x1024 transpose
// ---------------------------------------------------------------------------
__global__ void k_transpose(const float* __restrict__ S_, float* __restrict__ D_) {
    __shared__ float tile[32][33];
    int bx = blockIdx.x * 32, by = blockIdx.y * 32;
    int tx = threadIdx.x, ty = threadIdx.y;   // (32,8)
#pragma unroll
    for (int k = 0; k < 32; k += 8)
        tile[ty + k][tx] = S_[(size_t)(by + ty + k) * 1024 + bx + tx];
    __syncthreads();
#pragma unroll
    for (int k = 0; k < 32; k += 8)
        D_[(size_t)(bx + ty + k) * 1024 + by + tx] = tile[tx][ty + k];
}

// ---------------------------------------------------------------------------
// RMS norm rows of 1024 (no learned scale). dst2 optional second copy.
// ---------------------------------------------------------------------------
__global__ void k_rownorm(const float* __restrict__ src, float* __restrict__ dst,
                          float* __restrict__ dst2) {
    int r = blockIdx.x, tid = threadIdx.x;
    __shared__ float red[8];
    const float* row = src + (size_t)r * 1024;
    float ss = 0.f;
    for (int c = tid; c < 1024; c += 256) { float v = row[c]; ss += v * v; }
#pragma unroll
    for (int o = 16; o; o >>= 1) ss += __shfl_xor_sync(0xffffffffu, ss, o);
    if ((tid & 31) == 0) red[tid >> 5] = ss;
    __syncthreads();
    if (tid == 0) {
        float v = 0.f;
#pragma unroll
        for (int k = 0; k < 8; k++) v += red[k];
        red[0] = v;
    }
    __syncthreads();
    float scale = rsqrtf(red[0] * (1.0f / 1024.0f) + 1e-6f);
    for (int c = tid; c < 1024; c += 256) {
        float v = row[c] * scale;
        dst[(size_t)r * 1024 + c] = v;
        if (dst2) dst2[(size_t)r * 1024 + c] = v;
    }
}

// ---------------------------------------------------------------------------
// Generic small GEMM: C[rows, Ccols] = A[rows,1024] @ W[1024,Ccols]
// block: 128 threads = one 128-col chunk; blockIdx.y = rowgroup of RG rows.
// f32x2 packed over the K (c) dimension.
// ---------------------------------------------------------------------------
template <int RG>
__global__ __launch_bounds__(128) void k_gemm(const float* __restrict__ A,
                                              const float* __restrict__ W,
                                              float* __restrict__ C, int Ccols) {
    __shared__ float As[RG * 1024];
    int rbase = blockIdx.y * RG;
    int j = blockIdx.x * 128 + threadIdx.x;
    const float* Ab = A + (size_t)rbase * 1024;   // rows contiguous
    for (int i = threadIdx.x; i < RG * 1024; i += 128) As[i] = Ab[i];
    __syncthreads();
    const ull* A2 = (const ull*)As;
    ull acc[RG];
#pragma unroll
    for (int r = 0; r < RG; r++) acc[r] = 0ull;
    for (int cp = 0; cp < 512; ++cp) {
        float w0 = W[(size_t)(2 * cp) * Ccols + j];
        float w1 = W[(size_t)(2 * cp + 1) * Ccols + j];
        ull w2 = pk2(w0, w1);
#pragma unroll
        for (int r = 0; r < RG; r++) fma2(acc[r], w2, A2[r * 512 + cp]);
    }
#pragma unroll
    for (int r = 0; r < RG; r++) {
        float2 f = upk2(acc[r]);
        C[(size_t)(rbase + r) * Ccols + j] = f.x + f.y;
    }
}

// ---------------------------------------------------------------------------
// a[s][h][c] = sum_d WwkT[h*128+d][c] * q[s][h*128+d]
// grid (8 cchunks, 16 s), 128 threads
// ---------------------------------------------------------------------------
__global__ __launch_bounds__(128) void k_a(const float* __restrict__ WwkT,
                                           const float* __restrict__ Q,
                                           float* __restrict__ A) {
    int s = blockIdx.y;
    int c = blockIdx.x * 128 + threadIdx.x;
    __shared__ float qs[1024];
    for (int i = threadIdx.x; i < 1024; i += 128) qs[i] = Q[(size_t)s * 1024 + i];
    __syncthreads();
#pragma unroll
    for (int h = 0; h < 8; ++h) {
        float acc = 0.f;
#pragma unroll 8
        for (int d = 0; d < 128; ++d)
            acc += WwkT[(size_t)(h * 128 + d) * 1024 + c] * qs[h * 128 + d];
        A[(size_t)(s * 8 + h) * 1024 + c] = acc;
    }
}

// ---------------------------------------------------------------------------
// write_memory scores: raw score[seg][h][l] = (x[b,s,l]·a[s,h]) / sqrt(128)
// grid 128 = (seg*2+half), 256 threads (8 warps x 32 tokens)
// ---------------------------------------------------------------------------
__global__ __launch_bounds__(256) void k_scores(const float* __restrict__ x,
                                                const float* __restrict__ A,
                                                float* __restrict__ SC) {
    int blk = blockIdx.x;
    int seg = blk >> 1, half = blk & 1;
    int s = seg & 15, b = seg >> 4;
    __shared__ float asm_[8 * 1024];
    const float* asrc = A + (size_t)s * 8192;
    for (int i = threadIdx.x; i < 8192; i += 256) asm_[i] = asrc[i];
    __syncthreads();
    const ull* a2 = (const ull*)asm_;            // [h][512]
    int warp = threadIdx.x >> 5, lane = threadIdx.x & 31;
    for (int tk = 0; tk < 32; ++tk) {
        int l = half * 256 + warp * 32 + tk;
        const ull* xrow = (const ull*)x + (size_t)(b * 8192 + s * 512 + l) * 512;
        ull acc[8];
#pragma unroll
        for (int h = 0; h < 8; h++) acc[h] = 0ull;
#pragma unroll
        for (int i = 0; i < 16; ++i) {
            int c = lane + 32 * i;
            ull xv = xrow[c];
#pragma unroll
            for (int h = 0; h < 8; h++) fma2(acc[h], xv, a2[h * 512 + c]);
        }
#pragma unroll
        for (int h = 0; h < 8; h++) {
            float2 f = upk2(acc[h]);
            float v = f.x + f.y;
            v += __shfl_xor_sync(0xffffffffu, v, 16);
            v += __shfl_xor_sync(0xffffffffu, v, 8);
            v += __shfl_xor_sync(0xffffffffu, v, 4);
            v += __shfl_xor_sync(0xffffffffu, v, 2);
            v += __shfl_xor_sync(0xffffffffu, v, 1);
            if (lane == 0)
                SC[(size_t)seg * 4096 + h * 512 + l] = v * 0.08838834764831845f;
        }
    }
}

// ---------------------------------------------------------------------------
// softmax over l=512 per (seg,h); overwrites SC with normalized weights
// grid 64, 256 threads
// ---------------------------------------------------------------------------
__global__ __launch_bounds__(256) void k_softmax(float* __restrict__ SC) {
    int seg = blockIdx.x, tid = threadIdx.x;
    int warp = tid >> 5, lane = tid & 31;
    float* sc = SC + (size_t)seg * 4096;
    __shared__ float red[8];
    __shared__ float bmax, bsum;
    for (int h = 0; h < 8; ++h) {
        float v0 = sc[h * 512 + tid], v1 = sc[h * 512 + tid + 256];
        float m = fmaxf(v0, v1);
#pragma unroll
        for (int o = 16; o; o >>= 1) m = fmaxf(m, __shfl_xor_sync(0xffffffffu, m, o));
        if (lane == 0) red[warp] = m;
        __syncthreads();
        if (tid == 0) {
            float mm = red[0];
#pragma unroll
            for (int k = 1; k < 8; k++) mm = fmaxf(mm, red[k]);
            bmax = mm;
        }
        __syncthreads();
        float M = bmax;
        float e0 = __expf(v0 - M), e1 = __expf(v1 - M);
        float su = e0 + e1;
#pragma unroll
        for (int o = 16; o; o >>= 1) su += __shfl_xor_sync(0xffffffffu, su, o);
        if (lane == 0) red[warp] = su;
        __syncthreads();
        if (tid == 0) {
            float sm = 0.f;
#pragma unroll
            for (int k = 0; k < 8; k++) sm += red[k];
            bsum = sm;
        }
        __syncthreads();
        float inv = 1.0f / bsum;
        sc[h * 512 + tid] = e0 * inv;
        sc[h * 512 + tid + 256] = e1 * inv;
        __syncthreads();
    }
}

// ---------------------------------------------------------------------------
// y[seg][h][c] = sum_l w[h][l] * x[b,s,l,c]   (attn-weighted x average)
// grid (2 chalf, 64 seg), 256 threads; f32x2 packed over l-pairs
// ---------------------------------------------------------------------------
__global__ __launch_bounds__(256) void k_y(const float* __restrict__ x,
                                           const float* __restrict__ SC,
                                           float* __restrict__ Y) {
    int seg = blockIdx.y, chalf = blockIdx.x;
    int s = seg & 15, b = seg >> 4;
    __shared__ float wsm[8 * 512];
    const float* wsrc = SC + (size_t)seg * 4096;
    for (int i = threadIdx.x; i < 4096; i += 256) wsm[i] = wsrc[i];
    __syncthreads();
    const ull* w2 = (const ull*)wsm;             // [h][256] l-pairs
    int c0 = chalf * 512 + threadIdx.x;
    int c1 = c0 + 256;
    const float* xb = x + (size_t)(b * 8192 + s * 512) * 1024;
    ull acc0[8], acc1[8];
#pragma unroll
    for (int h = 0; h < 8; h++) { acc0[h] = 0ull; acc1[h] = 0ull; }
    for (int lp = 0; lp < 256; ++lp) {
        float xa0 = xb[(size_t)(2 * lp) * 1024 + c0];
        float xa1 = xb[(size_t)(2 * lp + 1) * 1024 + c0];
        float xb0 = xb[(size_t)(2 * lp) * 1024 + c1];
        float xb1 = xb[(size_t)(2 * lp + 1) * 1024 + c1];
        ull xpa = pk2(xa0, xa1), xpb = pk2(xb0, xb1);
#pragma unroll
        for (int h = 0; h < 8; h++) {
            ull wv = w2[h * 256 + lp];
            fma2(acc0[h], xpa, wv);
            fma2(acc1[h], xpb, wv);
        }
    }
#pragma unroll
    for (int h = 0; h < 8; h++) {
        float2 f0 = upk2(acc0[h]), f1 = upk2(acc1[h]);
        Y[(size_t)(seg * 8 + h) * 1024 + c0] = f0.x + f0.y;
        Y[(size_t)(seg * 8 + h) * 1024 + c1] = f1.x + f1.y;
    }
}

// ---------------------------------------------------------------------------
// mem0[seg][h*128+j] = sum_c y[seg][h][c] * Wwv[c][h*128+j]
// grid (8 h, 8 rowgroups of 8 segs), 128 threads
// ---------------------------------------------------------------------------
__global__ __launch_bounds__(128) void k_mem0(const float* __restrict__ Y,
                                              const float* __restrict__ Wwv,
                                              float* __restrict__ MEM0) {
    int h = blockIdx.x, rbase = blockIdx.y * 8;
    __shared__ float As[8 * 1024];
    for (int i = threadIdx.x; i < 8192; i += 128) {
        int r = i >> 10, c = i & 1023;
        As[i] = Y[(size_t)((rbase + r) * 8 + h) * 1024 + c];
    }
    __syncthreads();
    const ull* A2 = (const ull*)As;
    int j = h * 128 + threadIdx.x;
    ull acc[8];
#pragma unroll
    for (int r = 0; r < 8; r++) acc[r] = 0ull;
    for (int cp = 0; cp < 512; ++cp) {
        float w0 = Wwv[(size_t)(2 * cp) * 1024 + j];
        float w1 = Wwv[(size_t)(2 * cp + 1) * 1024 + j];
        ull w2 = pk2(w0, w1);
#pragma unroll
        for (int r = 0; r < 8; r++) fma2(acc[r], w2, A2[r * 512 + cp]);
    }
#pragma unroll
    for (int r = 0; r < 8; r++) {
        float2 f = upk2(acc[r]);
        MEM0[(size_t)(rbase + r) * 1024 + j] = f.x + f.y;
    }
}

// ---------------------------------------------------------------------------
// causal self-attention over S=16 slots, per (b,h). grid 32, 256 threads
// ---------------------------------------------------------------------------
__global__ __launch_bounds__(256) void k_slotattn(const float* __restrict__ QKV,
                                                  float* __restrict__ ATT) {
    int b = blockIdx.x >> 3, h = blockIdx.x & 7;
    __shared__ float qs[16][132], ks[16][132], vs[16][132];
    __shared__ float sc[16][17];
    int tid = threadIdx.x;
    for (int i = tid; i < 2048; i += 256) {
        int r = i >> 7, d = i & 127;
        size_t base = (size_t)(b * 16 + r) * 3072 + h * 128 + d;
        qs[r][d] = QKV[base];
        ks[r][d] = QKV[base + 1024];
        vs[r][d] = QKV[base + 2048];
    }
    __syncthreads();
    {
        int i = tid >> 4, jj = tid & 15;
        float dot = 0.f;
#pragma unroll 8
        for (int d = 0; d < 128; ++d) dot += qs[i][d] * ks[jj][d];
        sc[i][jj] = dot * 0.08838834764831845f;
    }
    __syncthreads();
    if (tid < 16) {
        int r = tid;
        float m = -1e30f;
        for (int j = 0; j <= r; ++j) m = fmaxf(m, sc[r][j]);
        float sum = 0.f;
        for (int j = 0; j < 16; ++j) {
            float e = (j <= r) ? __expf(sc[r][j] - m) : 0.f;
            sc[r][j] = e; sum += e;
        }
        float inv = 1.0f / sum;
        for (int j = 0; j < 16; ++j) sc[r][j] *= inv;
    }
    __syncthreads();
    {
        int d = tid & 127;
        int ibase = tid >> 7;   // 0 or 1
#pragma unroll
        for (int r = 0; r < 8; ++r) {
            int i = ibase + 2 * r;
            float o = 0.f;
#pragma unroll
            for (int j = 0; j < 16; ++j) o += sc[i][j] * vs[j][d];
            ATT[(size_t)(b * 16 + i) * 1024 + h * 128 + d] = o;
        }
    }
}

// ---------------------------------------------------------------------------
// read_memory fused: per token, qk[s]=x·kk[b,s]/32, masked softmax over s,
// out = sum_s w[s]*vr[b,s]. kk & vr in 128KB dyn smem. 2 tokens per warp-iter.
// grid (32 chunks, 4 b), 256 threads
// ---------------------------------------------------------------------------
__global__ __launch_bounds__(256, 1) void k_read(const float* __restrict__ x,
                                                 const float* __restrict__ KK,
                                                 const float* __restrict__ VR,
                                                 float* __restrict__ out) {
    extern __shared__ float sm[];
    int b = blockIdx.y, chunk = blockIdx.x;
    const float* kksrc = KK + (size_t)b * 16384;
    const float* vrsrc = VR + (size_t)b * 16384;
    for (int i = threadIdx.x; i < 16384; i += 256) {
        sm[i] = kksrc[i];
        sm[16384 + i] = vrsrc[i];
    }
    __syncthreads();
    const ull* kk2 = (const ull*)sm;              // [s][512]
    const ull* vr2 = (const ull*)(sm + 16384);
    int warp = threadIdx.x >> 5, lane = threadIdx.x & 31;
    int tbase = chunk * 256 + warp * 32;

    for (int p = 0; p < 16; ++p) {
        int t0 = tbase + 2 * p;
        int t1 = t0 + 1;
        int seg = t0 >> 9;   // same for t0,t1 (512-aligned pairs)
        const ull* xa = (const ull*)x + (size_t)(b * 8192 + t0) * 512;
        const ull* xb = xa + 512;
        ull acca[16], accb[16];
#pragma unroll
        for (int s = 0; s < 16; s++) { acca[s] = 0ull; accb[s] = 0ull; }
#pragma unroll
        for (int i = 0; i < 16; ++i) {
            int c = lane + 32 * i;
            ull va = xa[c], vb = xb[c];
#pragma unroll
            for (int s = 0; s < 16; s++) {
                ull kv = kk2[s * 512 + c];
                fma2(acca[s], va, kv);
                fma2(accb[s], vb, kv);
            }
        }
        float qa[16], qb[16];
#pragma unroll
        for (int s = 0; s < 16; s++) {
            float2 fa = upk2(acca[s]);
            float va = fa.x + fa.y;
            va += __shfl_xor_sync(0xffffffffu, va, 16);
            va += __shfl_xor_sync(0xffffffffu, va, 8);
            va += __shfl_xor_sync(0xffffffffu, va, 4);
            va += __shfl_xor_sync(0xffffffffu, va, 2);
            va += __shfl_xor_sync(0xffffffffu, va, 1);
            qa[s] = va * 0.03125f;
            float2 fb = upk2(accb[s]);
            float vb = fb.x + fb.y;
            vb += __shfl_xor_sync(0xffffffffu, vb, 16);
            vb += __shfl_xor_sync(0xffffffffu, vb, 8);
            vb += __shfl_xor_sync(0xffffffffu, vb, 4);
            vb += __shfl_xor_sync(0xffffffffu, vb, 2);
            vb += __shfl_xor_sync(0xffffffffu, vb, 1);
            qb[s] = vb * 0.03125f;
        }
        // masked softmax over s >= seg (all lanes redundant — values identical)
        float ma = -1e30f, mb = -1e30f;
#pragma unroll
        for (int s = 0; s < 16; s++) {
            if (s >= seg) { ma = fmaxf(ma, qa[s]); mb = fmaxf(mb, qb[s]); }
        }
        float sa = 0.f, sb = 0.f;
#pragma unroll
        for (int s = 0; s < 16; s++) {
            float ea = (s >= seg) ? __expf(qa[s] - ma) : 0.f;
            float eb = (s >= seg) ? __expf(qb[s] - mb) : 0.f;
            qa[s] = ea; qb[s] = eb; sa += ea; sb += eb;
        }
        float ia = 1.0f / sa, ib = 1.0f / sb;
        ull wa[16], wb[16];
#pragma unroll
        for (int s = 0; s < 16; s++) {
            float a = qa[s] * ia, c = qb[s] * ib;
            wa[s] = pk2(a, a);
            wb[s] = pk2(c, c);
        }
        // output
        ull* oa = (ull*)out + (size_t)(b * 8192 + t0) * 512;
        ull* ob = oa + 512;
#pragma unroll
        for (int i = 0; i < 16; ++i) {
            int c = lane + 32 * i;
            ull accoa = 0ull, accob = 0ull;
#pragma unroll
            for (int s = 0; s < 16; s++) {
                ull v = vr2[s * 512 + c];
                fma2(accoa, wa[s], v);
                fma2(accob, wb[s], v);
            }
            oa[c] = accoa;
            ob[c] = accob;
        }
    }
}

// ---------------------------------------------------------------------------
extern "C" void kernel_launch(void* const* d_in, const int* in_sizes, int n_in,
                              void* d_out, int out_size) {
    const float* x     = (const float*)d_in[0];
    const float* slots = (const float*)d_in[1];
    const float* Wrq   = (const float*)d_in[2];
    const float* Wrk   = (const float*)d_in[3];
    const float* Wrv   = (const float*)d_in[4];
    const float* Wwq   = (const float*)d_in[5];
    const float* Wwk   = (const float*)d_in[6];
    const float* Wwv   = (const float*)d_in[7];
    const float* Wqkv  = (const float*)d_in[8];
    const float* Wproj = (const float*)d_in[9];
    float* out    = (float*)d_out;
    float* outmem = out + OUT_ELEMS;

    float* scr = nullptr;
    cudaGetSymbolAddress((void**)&scr, g_scratch);

    cudaFuncSetAttribute(k_read, cudaFuncAttributeMaxDynamicSharedMemorySize, 131072);

    float* NS   = scr + OFF_NS;
    float* Q    = scr + OFF_Q;
    float* A    = scr + OFF_A;
    float* WWKT = scr + OFF_WWKT;
    float* WRQT = scr + OFF_WRQT;
    float* SC   = scr + OFF_SC;
    float* Y    = scr + OFF_Y;
    float* MEM0 = scr + OFF_MEM0;
    float* QKV  = scr + OFF_QKV;
    float* ATT  = scr + OFF_ATT;
    float* PROJ = scr + OFF_PROJ;
    float* MEMN = scr + OFF_MEMN;
    float* KR   = scr + OFF_KR;
    float* VR   = scr + OFF_VR;
    float* KK   = scr + OFF_KK;

    // transposes (Wwk, Wrq)
    k_transpose<<<dim3(32, 32), dim3(32, 8)>>>(Wwk, WWKT);
    k_transpose<<<dim3(32, 32), dim3(32, 8)>>>(Wrq, WRQT);

    // ---- write_memory ----
    k_rownorm<<<16, 256>>>(slots, NS, nullptr);
    k_gemm<4><<<dim3(8, 4), 128>>>(NS, Wwq, Q, 1024);
    k_a<<<dim3(8, 16), 128>>>(WWKT, Q, A);
    k_scores<<<128, 256>>>(x, A, SC);
    k_softmax<<<64, 256>>>(SC);
    k_y<<<dim3(2, 64), 256>>>(x, SC, Y);
    k_mem0<<<dim3(8, 8), 128>>>(Y, Wwv, MEM0);

    // ---- write_attn ----
    k_gemm<8><<<dim3(24, 8), 128>>>(MEM0, Wqkv, QKV, 3072);
    k_slotattn<<<32, 256>>>(QKV, ATT);
    k_gemm<8><<<dim3(8, 8), 128>>>(ATT, Wproj, PROJ, 1024);
    k_rownorm<<<64, 256>>>(PROJ, MEMN, outmem);   // also writes memory output

    // ---- read_memory ----
    k_gemm<8><<<dim3(8, 8), 128>>>(MEMN, Wrk, KR, 1024);
    k_gemm<8><<<dim3(8, 8), 128>>>(MEMN, Wrv, VR, 1024);
    k_gemm<8><<<dim3(8, 8), 128>>>(KR, WRQT, KK, 1024);
    k_read<<<dim3(32, 4), 256, 131072>>>(x, KK, VR, out);

    (void)in_sizes; (void)n_in; (void)out_size;
}

// round 12
// speedup vs baseline: 1.1778x; 1.1778x over previous
#include <cuda_runtime.h>

// ---------------------------------------------------------------------------
// Shapes: B=4, T=8192, D=1024, S=16 slots, H=8 heads, HD=128, segL=512
// ---------------------------------------------------------------------------
typedef unsigned long long ull;

#define OUT_ELEMS   33554432u   // 4*8192*1024
#define MEM_ELEMS   65536u      // 4*16*1024

// scratch offsets (floats)
#define OFF_NS     0u           // normed mem_slots        [16,1024]
#define OFF_Q      16384u       // q slots                 [16,1024]
#define OFF_A      32768u       // a[s][h][c]              [16,8,1024]
#define OFF_WWKT   163840u      // Wwk^T                   [1024,1024]
#define OFF_WRQT   1212416u     // Wrq^T                   [1024,1024]
#define OFF_SC     2260992u     // scores/weights          [64][8][512]
#define OFF_Y      2523136u     // y[seg][h][c]            [64,8,1024]
#define OFF_MEM0   3047424u     // mem after write_memory  [64,1024]
#define OFF_QKV    3112960u     // qkv                     [64,3072]
#define OFF_ATT    3309568u     // slot-attn out           [64,1024]
#define OFF_PROJ   3375104u     // proj pre-norm           [64,1024]
#define OFF_MEMN   3440640u     // normed memory           [64,1024]
#define OFF_KR     3506176u     // memory@Wrk              [64,1024]
#define OFF_VR     3571712u     // memory@Wrv              [64,1024]
#define OFF_KK     3637248u     // kr@Wrq^T                [64,1024]
#define SCRATCH_FLOATS 3702784u

__device__ __align__(16) float g_scratch[SCRATCH_FLOATS];

// ---- packed f32x2 helpers (Blackwell FFMA2) --------------------------------
__device__ __forceinline__ ull pk2(float x, float y) {
    ull r; asm("mov.b64 %0,{%1,%2};" : "=l"(r) : "f"(x), "f"(y)); return r;
}
__device__ __forceinline__ float2 upk2(ull v) {
    float2 f; asm("mov.b64 {%0,%1},%2;" : "=f"(f.x), "=f"(f.y) : "l"(v)); return f;
}
__device__ __forceinline__ void fma2(ull& d, ull a, ull b) {
    asm("fma.rn.f32x2 %0,%1,%2,%0;" : "+l"(d) : "l"(a), "l"(b));
}

// ---------------------------------------------------------------------------
// 1024x1024 transpose
// ---------------------------------------------------------------------------
__global__ void k_transpose(const float* __restrict__ S_, float* __restrict__ D_) {
    __shared__ float tile[32][33];
    int bx = blockIdx.x * 32, by = blockIdx.y * 32;
    int tx = threadIdx.x, ty = threadIdx.y;   // (32,8)
#pragma unroll
    for (int k = 0; k < 32; k += 8)
        tile[ty + k][tx] = S_[(size_t)(by + ty + k) * 1024 + bx + tx];
    __syncthreads();
#pragma unroll
    for (int k = 0; k < 32; k += 8)
        D_[(size_t)(bx + ty + k) * 1024 + by + tx] = tile[tx][ty + k];
}

// ---------------------------------------------------------------------------
// RMS norm rows of 1024 (no learned scale). dst2 optional second copy.
// ---------------------------------------------------------------------------
__global__ void k_rownorm(const float* __restrict__ src, float* __restrict__ dst,
                          float* __restrict__ dst2) {
    int r = blockIdx.x, tid = threadIdx.x;
    __shared__ float red[8];
    const float* row = src + (size_t)r * 1024;
    float ss = 0.f;
    for (int c = tid; c < 1024; c += 256) { float v = row[c]; ss += v * v; }
#pragma unroll
    for (int o = 16; o; o >>= 1) ss += __shfl_xor_sync(0xffffffffu, ss, o);
    if ((tid & 31) == 0) red[tid >> 5] = ss;
    __syncthreads();
    if (tid == 0) {
        float v = 0.f;
#pragma unroll
        for (int k = 0; k < 8; k++) v += red[k];
        red[0] = v;
    }
    __syncthreads();
    float scale = rsqrtf(red[0] * (1.0f / 1024.0f) + 1e-6f);
    for (int c = tid; c < 1024; c += 256) {
        float v = row[c] * scale;
        dst[(size_t)r * 1024 + c] = v;
        if (dst2) dst2[(size_t)r * 1024 + c] = v;
    }
}

// ---------------------------------------------------------------------------
// Small GEMM: C[rows,Ccols] = A[rows,1024] @ W[1024,Ccols]
// K-loop unrolled x8 with all 16 W loads hoisted (MLP=16) — this was the
// latency bottleneck in R7 (129us for a 16-row GEMM).
// ---------------------------------------------------------------------------
template <int RG>
__global__ __launch_bounds__(128) void k_gemm(const float* __restrict__ A,
                                              const float* __restrict__ W,
                                              float* __restrict__ C, int Ccols) {
    __shared__ float As[RG * 1024];
    int rbase = blockIdx.y * RG;
    int j = blockIdx.x * 128 + threadIdx.x;
    const float* Ab = A + (size_t)rbase * 1024;
    for (int i = threadIdx.x; i < RG * 1024; i += 128) As[i] = Ab[i];
    __syncthreads();
    const ull* A2 = (const ull*)As;
    const float* Wj = W + j;
    ull acc[RG];
#pragma unroll
    for (int r = 0; r < RG; r++) acc[r] = 0ull;
    for (int cp0 = 0; cp0 < 512; cp0 += 8) {
        float wv[16];
#pragma unroll
        for (int u = 0; u < 16; u++)
            wv[u] = Wj[(size_t)(2 * cp0 + u) * Ccols];
#pragma unroll
        for (int u = 0; u < 8; u++) {
            ull w2 = pk2(wv[2 * u], wv[2 * u + 1]);
#pragma unroll
            for (int r = 0; r < RG; r++) fma2(acc[r], w2, A2[r * 512 + cp0 + u]);
        }
    }
#pragma unroll
    for (int r = 0; r < RG; r++) {
        float2 f = upk2(acc[r]);
        C[(size_t)(rbase + r) * Ccols + j] = f.x + f.y;
    }
}

// ---------------------------------------------------------------------------
// a[s][h][c] = sum_d WwkT[h*128+d][c] * q[s][h*128+d]
// grid (4 cchunks, 4 sgroups), 256 threads. q packed in s-pairs in smem;
// W loads batched x8 for MLP.
// ---------------------------------------------------------------------------
__global__ __launch_bounds__(256) void k_a(const float* __restrict__ WwkT,
                                           const float* __restrict__ Q,
                                           float* __restrict__ A) {
    int s0 = blockIdx.y * 4;
    int c = blockIdx.x * 256 + threadIdx.x;
    __shared__ ull qp[2][1024];
    for (int k = threadIdx.x; k < 1024; k += 256) {
        qp[0][k] = pk2(Q[(size_t)(s0 + 0) * 1024 + k], Q[(size_t)(s0 + 1) * 1024 + k]);
        qp[1][k] = pk2(Q[(size_t)(s0 + 2) * 1024 + k], Q[(size_t)(s0 + 3) * 1024 + k]);
    }
    __syncthreads();
    const float* Wc = WwkT + c;
#pragma unroll
    for (int h = 0; h < 8; ++h) {
        ull acc0 = 0ull, acc1 = 0ull;
        for (int d0 = 0; d0 < 128; d0 += 8) {
            float wv[8];
#pragma unroll
            for (int u = 0; u < 8; u++)
                wv[u] = Wc[(size_t)(h * 128 + d0 + u) * 1024];
#pragma unroll
            for (int u = 0; u < 8; u++) {
                ull ww = pk2(wv[u], wv[u]);
                int k = h * 128 + d0 + u;
                fma2(acc0, ww, qp[0][k]);
                fma2(acc1, ww, qp[1][k]);
            }
        }
        float2 f0 = upk2(acc0), f1 = upk2(acc1);
        A[(size_t)((s0 + 0) * 8 + h) * 1024 + c] = f0.x;
        A[(size_t)((s0 + 1) * 8 + h) * 1024 + c] = f0.y;
        A[(size_t)((s0 + 2) * 8 + h) * 1024 + c] = f1.x;
        A[(size_t)((s0 + 3) * 8 + h) * 1024 + c] = f1.y;
    }
}

// ---------------------------------------------------------------------------
// write_memory scores: raw score[seg][h][l] = (x[b,s,l]·a[s,h]) / sqrt(128)
// grid 128 = (seg*2+half), 256 threads (8 warps x 32 tokens)
// ---------------------------------------------------------------------------
__global__ __launch_bounds__(256) void k_scores(const float* __restrict__ x,
                                                const float* __restrict__ A,
                                                float* __restrict__ SC) {
    int blk = blockIdx.x;
    int seg = blk >> 1, half = blk & 1;
    int s = seg & 15, b = seg >> 4;
    __shared__ float asm_[8 * 1024];
    const float* asrc = A + (size_t)s * 8192;
    for (int i = threadIdx.x; i < 8192; i += 256) asm_[i] = asrc[i];
    __syncthreads();
    const ull* a2 = (const ull*)asm_;            // [h][512]
    int warp = threadIdx.x >> 5, lane = threadIdx.x & 31;
    for (int tk = 0; tk < 32; ++tk) {
        int l = half * 256 + warp * 32 + tk;
        const ull* xrow = (const ull*)x + (size_t)(b * 8192 + s * 512 + l) * 512;
        ull acc[8];
#pragma unroll
        for (int h = 0; h < 8; h++) acc[h] = 0ull;
#pragma unroll
        for (int i = 0; i < 16; ++i) {
            int c = lane + 32 * i;
            ull xv = xrow[c];
#pragma unroll
            for (int h = 0; h < 8; h++) fma2(acc[h], xv, a2[h * 512 + c]);
        }
#pragma unroll
        for (int h = 0; h < 8; h++) {
            float2 f = upk2(acc[h]);
            float v = f.x + f.y;
            v += __shfl_xor_sync(0xffffffffu, v, 16);
            v += __shfl_xor_sync(0xffffffffu, v, 8);
            v += __shfl_xor_sync(0xffffffffu, v, 4);
            v += __shfl_xor_sync(0xffffffffu, v, 2);
            v += __shfl_xor_sync(0xffffffffu, v, 1);
            if (lane == 0)
                SC[(size_t)seg * 4096 + h * 512 + l] = v * 0.08838834764831845f;
        }
    }
}

// ---------------------------------------------------------------------------
// softmax over l=512 per (seg,h); overwrites SC with normalized weights
// ---------------------------------------------------------------------------
__global__ __launch_bounds__(256) void k_softmax(float* __restrict__ SC) {
    int seg = blockIdx.x, tid = threadIdx.x;
    int warp = tid >> 5, lane = tid & 31;
    float* sc = SC + (size_t)seg * 4096;
    __shared__ float red[8];
    __shared__ float bmax, bsum;
    for (int h = 0; h < 8; ++h) {
        float v0 = sc[h * 512 + tid], v1 = sc[h * 512 + tid + 256];
        float m = fmaxf(v0, v1);
#pragma unroll
        for (int o = 16; o; o >>= 1) m = fmaxf(m, __shfl_xor_sync(0xffffffffu, m, o));
        if (lane == 0) red[warp] = m;
        __syncthreads();
        if (tid == 0) {
            float mm = red[0];
#pragma unroll
            for (int k = 1; k < 8; k++) mm = fmaxf(mm, red[k]);
            bmax = mm;
        }
        __syncthreads();
        float M = bmax;
        float e0 = __expf(v0 - M), e1 = __expf(v1 - M);
        float su = e0 + e1;
#pragma unroll
        for (int o = 16; o; o >>= 1) su += __shfl_xor_sync(0xffffffffu, su, o);
        if (lane == 0) red[warp] = su;
        __syncthreads();
        if (tid == 0) {
            float sm = 0.f;
#pragma unroll
            for (int k = 0; k < 8; k++) sm += red[k];
            bsum = sm;
        }
        __syncthreads();
        float inv = 1.0f / bsum;
        sc[h * 512 + tid] = e0 * inv;
        sc[h * 512 + tid + 256] = e1 * inv;
        __syncthreads();
    }
}

// ---------------------------------------------------------------------------
// y[seg][h][c] = sum_l w[h][l] * x[b,s,l,c]   (attn-weighted x average)
// grid (2 chalf, 64 seg), 256 threads; f32x2 packed over l-pairs
// ---------------------------------------------------------------------------
__global__ __launch_bounds__(256) void k_y(const float* __restrict__ x,
                                           const float* __restrict__ SC,
                                           float* __restrict__ Y) {
    int seg = blockIdx.y, chalf = blockIdx.x;
    int s = seg & 15, b = seg >> 4;
    __shared__ float wsm[8 * 512];
    const float* wsrc = SC + (size_t)seg * 4096;
    for (int i = threadIdx.x; i < 4096; i += 256) wsm[i] = wsrc[i];
    __syncthreads();
    const ull* w2 = (const ull*)wsm;             // [h][256] l-pairs
    int c0 = chalf * 512 + threadIdx.x;
    int c1 = c0 + 256;
    const float* xb = x + (size_t)(b * 8192 + s * 512) * 1024;
    ull acc0[8], acc1[8];
#pragma unroll
    for (int h = 0; h < 8; h++) { acc0[h] = 0ull; acc1[h] = 0ull; }
#pragma unroll 4
    for (int lp = 0; lp < 256; ++lp) {
        float xa0 = xb[(size_t)(2 * lp) * 1024 + c0];
        float xa1 = xb[(size_t)(2 * lp + 1) * 1024 + c0];
        float xb0 = xb[(size_t)(2 * lp) * 1024 + c1];
        float xb1 = xb[(size_t)(2 * lp + 1) * 1024 + c1];
        ull xpa = pk2(xa0, xa1), xpb = pk2(xb0, xb1);
#pragma unroll
        for (int h = 0; h < 8; h++) {
            ull wv = w2[h * 256 + lp];
            fma2(acc0[h], xpa, wv);
            fma2(acc1[h], xpb, wv);
        }
    }
#pragma unroll
    for (int h = 0; h < 8; h++) {
        float2 f0 = upk2(acc0[h]), f1 = upk2(acc1[h]);
        Y[(size_t)(seg * 8 + h) * 1024 + c0] = f0.x + f0.y;
        Y[(size_t)(seg * 8 + h) * 1024 + c1] = f1.x + f1.y;
    }
}

// ---------------------------------------------------------------------------
// mem0[seg][h*128+j] = sum_c y[seg][h][c] * Wwv[c][h*128+j]
// grid (8 h, 8 rowgroups of 8 segs), 128 threads; batched loads (MLP 16)
// ---------------------------------------------------------------------------
__global__ __launch_bounds__(128) void k_mem0(const float* __restrict__ Y,
                                              const float* __restrict__ Wwv,
                                              float* __restrict__ MEM0) {
    int h = blockIdx.x, rbase = blockIdx.y * 8;
    __shared__ float As[8 * 1024];
    for (int i = threadIdx.x; i < 8192; i += 128) {
        int r = i >> 10, c = i & 1023;
        As[i] = Y[(size_t)((rbase + r) * 8 + h) * 1024 + c];
    }
    __syncthreads();
    const ull* A2 = (const ull*)As;
    int j = h * 128 + threadIdx.x;
    const float* Wj = Wwv + j;
    ull acc[8];
#pragma unroll
    for (int r = 0; r < 8; r++) acc[r] = 0ull;
    for (int cp0 = 0; cp0 < 512; cp0 += 8) {
        float wv[16];
#pragma unroll
        for (int u = 0; u < 16; u++)
            wv[u] = Wj[(size_t)(2 * cp0 + u) * 1024];
#pragma unroll
        for (int u = 0; u < 8; u++) {
            ull w2 = pk2(wv[2 * u], wv[2 * u + 1]);
#pragma unroll
            for (int r = 0; r < 8; r++) fma2(acc[r], w2, A2[r * 512 + cp0 + u]);
        }
    }
#pragma unroll
    for (int r = 0; r < 8; r++) {
        float2 f = upk2(acc[r]);
        MEM0[(size_t)(rbase + r) * 1024 + j] = f.x + f.y;
    }
}

// ---------------------------------------------------------------------------
// causal self-attention over S=16 slots, per (b,h). grid 32, 256 threads
// ---------------------------------------------------------------------------
__global__ __launch_bounds__(256) void k_slotattn(const float* __restrict__ QKV,
                                                  float* __restrict__ ATT) {
    int b = blockIdx.x >> 3, h = blockIdx.x & 7;
    __shared__ float qs[16][132], ks[16][132], vs[16][132];
    __shared__ float sc[16][17];
    int tid = threadIdx.x;
    for (int i = tid; i < 2048; i += 256) {
        int r = i >> 7, d = i & 127;
        size_t base = (size_t)(b * 16 + r) * 3072 + h * 128 + d;
        qs[r][d] = QKV[base];
        ks[r][d] = QKV[base + 1024];
        vs[r][d] = QKV[base + 2048];
    }
    __syncthreads();
    {
        int i = tid >> 4, jj = tid & 15;
        float dot = 0.f;
#pragma unroll 8
        for (int d = 0; d < 128; ++d) dot += qs[i][d] * ks[jj][d];
        sc[i][jj] = dot * 0.08838834764831845f;
    }
    __syncthreads();
    if (tid < 16) {
        int r = tid;
        float m = -1e30f;
        for (int j = 0; j <= r; ++j) m = fmaxf(m, sc[r][j]);
        float sum = 0.f;
        for (int j = 0; j < 16; ++j) {
            float e = (j <= r) ? __expf(sc[r][j] - m) : 0.f;
            sc[r][j] = e; sum += e;
        }
        float inv = 1.0f / sum;
        for (int j = 0; j < 16; ++j) sc[r][j] *= inv;
    }
    __syncthreads();
    {
        int d = tid & 127;
        int ibase = tid >> 7;   // 0 or 1
#pragma unroll
        for (int r = 0; r < 8; ++r) {
            int i = ibase + 2 * r;
            float o = 0.f;
#pragma unroll
            for (int j = 0; j < 16; ++j) o += sc[i][j] * vs[j][d];
            ATT[(size_t)(b * 16 + i) * 1024 + h * 128 + d] = o;
        }
    }
}

// ---------------------------------------------------------------------------
// read_memory fused: per token, qk[s]=x·kk[b,s]/32, masked softmax over s,
// out = sum_s w[s]*vr[b,s]. kk & vr in 128KB dyn smem. 2 tokens per warp-iter.
// grid (32 chunks, 4 b), 256 threads
// ---------------------------------------------------------------------------
__global__ __launch_bounds__(256, 1) void k_read(const float* __restrict__ x,
                                                 const float* __restrict__ KK,
                                                 const float* __restrict__ VR,
                                                 float* __restrict__ out) {
    extern __shared__ float sm[];
    int b = blockIdx.y, chunk = blockIdx.x;
    const float* kksrc = KK + (size_t)b * 16384;
    const float* vrsrc = VR + (size_t)b * 16384;
    for (int i = threadIdx.x; i < 16384; i += 256) {
        sm[i] = kksrc[i];
        sm[16384 + i] = vrsrc[i];
    }
    __syncthreads();
    const ull* kk2 = (const ull*)sm;              // [s][512]
    const ull* vr2 = (const ull*)(sm + 16384);
    int warp = threadIdx.x >> 5, lane = threadIdx.x & 31;
    int tbase = chunk * 256 + warp * 32;

    for (int p = 0; p < 16; ++p) {
        int t0 = tbase + 2 * p;
        int seg = t0 >> 9;   // same for t0,t1 (512-aligned pairs)
        const ull* xa = (const ull*)x + (size_t)(b * 8192 + t0) * 512;
        const ull* xb = xa + 512;
        ull acca[16], accb[16];
#pragma unroll
        for (int s = 0; s < 16; s++) { acca[s] = 0ull; accb[s] = 0ull; }
#pragma unroll
        for (int i = 0; i < 16; ++i) {
            int c = lane + 32 * i;
            ull va = xa[c], vb = xb[c];
#pragma unroll
            for (int s = 0; s < 16; s++) {
                ull kv = kk2[s * 512 + c];
                fma2(acca[s], va, kv);
                fma2(accb[s], vb, kv);
            }
        }
        float qa[16], qb[16];
#pragma unroll
        for (int s = 0; s < 16; s++) {
            float2 fa = upk2(acca[s]);
            float va = fa.x + fa.y;
            va += __shfl_xor_sync(0xffffffffu, va, 16);
            va += __shfl_xor_sync(0xffffffffu, va, 8);
            va += __shfl_xor_sync(0xffffffffu, va, 4);
            va += __shfl_xor_sync(0xffffffffu, va, 2);
            va += __shfl_xor_sync(0xffffffffu, va, 1);
            qa[s] = va * 0.03125f;
            float2 fb = upk2(accb[s]);
            float vb = fb.x + fb.y;
            vb += __shfl_xor_sync(0xffffffffu, vb, 16);
            vb += __shfl_xor_sync(0xffffffffu, vb, 8);
            vb += __shfl_xor_sync(0xffffffffu, vb, 4);
            vb += __shfl_xor_sync(0xffffffffu, vb, 2);
            vb += __shfl_xor_sync(0xffffffffu, vb, 1);
            qb[s] = vb * 0.03125f;
        }
        float ma = -1e30f, mb = -1e30f;
#pragma unroll
        for (int s = 0; s < 16; s++) {
            if (s >= seg) { ma = fmaxf(ma, qa[s]); mb = fmaxf(mb, qb[s]); }
        }
        float sa = 0.f, sb = 0.f;
#pragma unroll
        for (int s = 0; s < 16; s++) {
            float ea = (s >= seg) ? __expf(qa[s] - ma) : 0.f;
            float eb = (s >= seg) ? __expf(qb[s] - mb) : 0.f;
            qa[s] = ea; qb[s] = eb; sa += ea; sb += eb;
        }
        float ia = 1.0f / sa, ib = 1.0f / sb;
        ull wa[16], wb[16];
#pragma unroll
        for (int s = 0; s < 16; s++) {
            float a = qa[s] * ia, c = qb[s] * ib;
            wa[s] = pk2(a, a);
            wb[s] = pk2(c, c);
        }
        ull* oa = (ull*)out + (size_t)(b * 8192 + t0) * 512;
        ull* ob = oa + 512;
#pragma unroll
        for (int i = 0; i < 16; ++i) {
            int c = lane + 32 * i;
            ull accoa = 0ull, accob = 0ull;
#pragma unroll
            for (int s = 0; s < 16; s++) {
                ull v = vr2[s * 512 + c];
                fma2(accoa, wa[s], v);
                fma2(accob, wb[s], v);
            }
            oa[c] = accoa;
            ob[c] = accob;
        }
    }
}

// ---------------------------------------------------------------------------
extern "C" void kernel_launch(void* const* d_in, const int* in_sizes, int n_in,
                              void* d_out, int out_size) {
    const float* x     = (const float*)d_in[0];
    const float* slots = (const float*)d_in[1];
    const float* Wrq   = (const float*)d_in[2];
    const float* Wrk   = (const float*)d_in[3];
    const float* Wrv   = (const float*)d_in[4];
    const float* Wwq   = (const float*)d_in[5];
    const float* Wwk   = (const float*)d_in[6];
    const float* Wwv   = (const float*)d_in[7];
    const float* Wqkv  = (const float*)d_in[8];
    const float* Wproj = (const float*)d_in[9];
    float* out    = (float*)d_out;
    float* outmem = out + OUT_ELEMS;

    float* scr = nullptr;
    cudaGetSymbolAddress((void**)&scr, g_scratch);

    cudaFuncSetAttribute(k_read, cudaFuncAttributeMaxDynamicSharedMemorySize, 131072);

    float* NS   = scr + OFF_NS;
    float* Q    = scr + OFF_Q;
    float* A    = scr + OFF_A;
    float* WWKT = scr + OFF_WWKT;
    float* WRQT = scr + OFF_WRQT;
    float* SC   = scr + OFF_SC;
    float* Y    = scr + OFF_Y;
    float* MEM0 = scr + OFF_MEM0;
    float* QKV  = scr + OFF_QKV;
    float* ATT  = scr + OFF_ATT;
    float* PROJ = scr + OFF_PROJ;
    float* MEMN = scr + OFF_MEMN;
    float* KR   = scr + OFF_KR;
    float* VR   = scr + OFF_VR;
    float* KK   = scr + OFF_KK;

    // transposes (Wwk, Wrq)
    k_transpose<<<dim3(32, 32), dim3(32, 8)>>>(Wwk, WWKT);
    k_transpose<<<dim3(32, 32), dim3(32, 8)>>>(Wrq, WRQT);

    // ---- write_memory ----
    k_rownorm<<<16, 256>>>(slots, NS, nullptr);
    k_gemm<4><<<dim3(8, 4), 128>>>(NS, Wwq, Q, 1024);
    k_a<<<dim3(4, 4), 256>>>(WWKT, Q, A);
    k_scores<<<128, 256>>>(x, A, SC);
    k_softmax<<<64, 256>>>(SC);
    k_y<<<dim3(2, 64), 256>>>(x, SC, Y);
    k_mem0<<<dim3(8, 8), 128>>>(Y, Wwv, MEM0);

    // ---- write_attn ----
    k_gemm<8><<<dim3(24, 8), 128>>>(MEM0, Wqkv, QKV, 3072);
    k_slotattn<<<32, 256>>>(QKV, ATT);
    k_gemm<8><<<dim3(8, 8), 128>>>(ATT, Wproj, PROJ, 1024);
    k_rownorm<<<64, 256>>>(PROJ, MEMN, outmem);   // also writes memory output

    // ---- read_memory ----
    k_gemm<8><<<dim3(8, 8), 128>>>(MEMN, Wrk, KR, 1024);
    k_gemm<8><<<dim3(8, 8), 128>>>(MEMN, Wrv, VR, 1024);
    k_gemm<8><<<dim3(8, 8), 128>>>(KR, WRQT, KK, 1024);
    k_read<<<dim3(32, 4), 256, 131072>>>(x, KK, VR, out);

    (void)in_sizes; (void)n_in; (void)out_size;
}

// round 13
// speedup vs baseline: 1.6630x; 1.4120x over previous
#include <cuda_runtime.h>

// ---------------------------------------------------------------------------
// Shapes: B=4, T=8192, D=1024, S=16 slots, H=8 heads, HD=128, segL=512
// ---------------------------------------------------------------------------
typedef unsigned long long ull;

#define OUT_ELEMS   33554432u   // 4*8192*1024

// scratch offsets (floats)
#define OFF_NS     0u           // normed mem_slots        [16,1024]
#define OFF_Q      16384u       // q slots                 [16,1024]
#define OFF_A      32768u       // a[s][h][c]              [16,8,1024]
#define OFF_WWKT   163840u      // Wwk^T                   [1024,1024]
#define OFF_WRQT   1212416u     // Wrq^T                   [1024,1024]
#define OFF_Y      2523136u     // y[seg][h][c]            [64,8,1024]
#define OFF_MEM0   3047424u     // mem after write_memory  [64,1024]
#define OFF_QKV    3112960u     // qkv                     [64,3072]
#define OFF_ATT    3309568u     // slot-attn out           [64,1024]
#define OFF_PROJ   3375104u     // proj pre-norm           [64,1024]
#define OFF_MEMN   3440640u     // normed memory           [64,1024]
#define OFF_KR     3506176u     // memory@Wrk              [64,1024]
#define OFF_VR     3571712u     // memory@Wrv              [64,1024]
#define OFF_KK     3637248u     // kr@Wrq^T                [64,1024]
#define SCRATCH_FLOATS 3702784u

__device__ __align__(16) float g_scratch[SCRATCH_FLOATS];

// ---- packed f32x2 helpers (Blackwell FFMA2) --------------------------------
__device__ __forceinline__ ull pk2(float x, float y) {
    ull r; asm("mov.b64 %0,{%1,%2};" : "=l"(r) : "f"(x), "f"(y)); return r;
}
__device__ __forceinline__ float2 upk2(ull v) {
    float2 f; asm("mov.b64 {%0,%1},%2;" : "=f"(f.x), "=f"(f.y) : "l"(v)); return f;
}
__device__ __forceinline__ void fma2(ull& d, ull a, ull b) {
    asm("fma.rn.f32x2 %0,%1,%2,%0;" : "+l"(d) : "l"(a), "l"(b));
}

// ---------------------------------------------------------------------------
// 1024x1024 transpose
// ---------------------------------------------------------------------------
__global__ void k_transpose(const float* __restrict__ S_, float* __restrict__ D_) {
    __shared__ float tile[32][33];
    int bx = blockIdx.x * 32, by = blockIdx.y * 32;
    int tx = threadIdx.x, ty = threadIdx.y;   // (32,8)
#pragma unroll
    for (int k = 0; k < 32; k += 8)
        tile[ty + k][tx] = S_[(size_t)(by + ty + k) * 1024 + bx + tx];
    __syncthreads();
#pragma unroll
    for (int k = 0; k < 32; k += 8)
        D_[(size_t)(bx + ty + k) * 1024 + by + tx] = tile[tx][ty + k];
}

// ---------------------------------------------------------------------------
// RMS norm rows of 1024 (no learned scale). dst2 optional second copy.
// ---------------------------------------------------------------------------
__global__ void k_rownorm(const float* __restrict__ src, float* __restrict__ dst,
                          float* __restrict__ dst2) {
    int r = blockIdx.x, tid = threadIdx.x;
    __shared__ float red[8];
    const float* row = src + (size_t)r * 1024;
    float ss = 0.f;
    for (int c = tid; c < 1024; c += 256) { float v = row[c]; ss += v * v; }
#pragma unroll
    for (int o = 16; o; o >>= 1) ss += __shfl_xor_sync(0xffffffffu, ss, o);
    if ((tid & 31) == 0) red[tid >> 5] = ss;
    __syncthreads();
    if (tid == 0) {
        float v = 0.f;
#pragma unroll
        for (int k = 0; k < 8; k++) v += red[k];
        red[0] = v;
    }
    __syncthreads();
    float scale = rsqrtf(red[0] * (1.0f / 1024.0f) + 1e-6f);
    for (int c = tid; c < 1024; c += 256) {
        float v = row[c] * scale;
        dst[(size_t)r * 1024 + c] = v;
        if (dst2) dst2[(size_t)r * 1024 + c] = v;
    }
}

// ---------------------------------------------------------------------------
// Tiled GEMM: C[rows,Ccols] = A[rows,1024] @ W[1024,Ccols]
// grid (Ccols/128, rows/8), 128 threads, dyn smem 64KB.
// W tiles (64 k-rows x 128 cols) loaded coalesced as float4 into a register
// prefetch buffer (software pipeline), staged through smem, FMA in f32x2.
// A-row gather: A row index = (rbase+r)*aStride + (aUseBx ? blockIdx.x : 0).
// ---------------------------------------------------------------------------
__global__ __launch_bounds__(128, 1) void k_tgemm(const float* __restrict__ A,
                                                  const float* __restrict__ W,
                                                  float* __restrict__ C, int Ccols,
                                                  int aStride, int aUseBx) {
    extern __shared__ float dsm[];
    float* As = dsm;              // 8*1024
    float* Ws = dsm + 8192;       // 64*128
    int rbase = blockIdx.y * 8;
    int jbase = blockIdx.x * 128;
    int aOff = aUseBx ? blockIdx.x : 0;
    int tid = threadIdx.x;

    // load A rows (gathered, float4 coalesced)
#pragma unroll
    for (int r = 0; r < 8; r++) {
        const float4* src = (const float4*)(A + (size_t)((rbase + r) * aStride + aOff) * 1024);
        float4* dst = (float4*)(As + r * 1024);
        dst[tid] = src[tid];
        dst[tid + 128] = src[tid + 128];
    }

    // prefetch W tile 0 into registers
    const float* Wbase = W + jbase;
    float4 wreg[16];
#pragma unroll
    for (int i = 0; i < 16; i++) {
        int idx = tid + 128 * i;
        wreg[i] = *(const float4*)(Wbase + (size_t)(idx >> 5) * Ccols + (idx & 31) * 4);
    }
    __syncthreads();

    const ull* A2 = (const ull*)As;
    ull acc[8];
#pragma unroll
    for (int r = 0; r < 8; r++) acc[r] = 0ull;

    for (int t = 0; t < 16; t++) {
        float4* Ws4 = (float4*)Ws;
#pragma unroll
        for (int i = 0; i < 16; i++) Ws4[tid + 128 * i] = wreg[i];
        __syncthreads();
        if (t < 15) {
            const float* Wn = Wbase + (size_t)(t + 1) * 64 * Ccols;
#pragma unroll
            for (int i = 0; i < 16; i++) {
                int idx = tid + 128 * i;
                wreg[i] = *(const float4*)(Wn + (size_t)(idx >> 5) * Ccols + (idx & 31) * 4);
            }
        }
#pragma unroll
        for (int p = 0; p < 32; p++) {
            ull w2 = pk2(Ws[(2 * p) * 128 + tid], Ws[(2 * p + 1) * 128 + tid]);
#pragma unroll
            for (int r = 0; r < 8; r++) fma2(acc[r], w2, A2[r * 512 + t * 32 + p]);
        }
        __syncthreads();
    }
#pragma unroll
    for (int r = 0; r < 8; r++) {
        float2 f = upk2(acc[r]);
        C[(size_t)(rbase + r) * Ccols + jbase + tid] = f.x + f.y;
    }
}

// ---------------------------------------------------------------------------
// a[s][h][c] = sum_d WwkT[h*128+d][c] * q[s][h*128+d]
// per-h sliced tile GEMM: grid (8 jchunks, 8 h), 128 threads.
// ---------------------------------------------------------------------------
__global__ __launch_bounds__(128, 1) void k_a2(const float* __restrict__ WwkT,
                                               const float* __restrict__ Q,
                                               float* __restrict__ A) {
    __shared__ float Qs[16 * 128];   // 8 KB
    __shared__ float Ws[64 * 128];   // 32 KB
    int h = blockIdx.y;
    int jbase = blockIdx.x * 128;
    int tid = threadIdx.x;

    for (int i = tid; i < 512; i += 128) {
        int s = i >> 5, c4 = i & 31;
        ((float4*)Qs)[i] = *(const float4*)(Q + (size_t)s * 1024 + h * 128 + c4 * 4);
    }

    const float* Wbase = WwkT + (size_t)h * 128 * 1024 + jbase;
    float4 wreg[16];
#pragma unroll
    for (int i = 0; i < 16; i++) {
        int idx = tid + 128 * i;
        wreg[i] = *(const float4*)(Wbase + (size_t)(idx >> 5) * 1024 + (idx & 31) * 4);
    }
    __syncthreads();

    const ull* Q2 = (const ull*)Qs;   // [16][64]
    ull acc[16];
#pragma unroll
    for (int s = 0; s < 16; s++) acc[s] = 0ull;

    for (int t = 0; t < 2; t++) {
        float4* Ws4 = (float4*)Ws;
#pragma unroll
        for (int i = 0; i < 16; i++) Ws4[tid + 128 * i] = wreg[i];
        __syncthreads();
        if (t == 0) {
            const float* Wn = Wbase + (size_t)64 * 1024;
#pragma unroll
            for (int i = 0; i < 16; i++) {
                int idx = tid + 128 * i;
                wreg[i] = *(const float4*)(Wn + (size_t)(idx >> 5) * 1024 + (idx & 31) * 4);
            }
        }
#pragma unroll
        for (int p = 0; p < 32; p++) {
            ull w2 = pk2(Ws[(2 * p) * 128 + tid], Ws[(2 * p + 1) * 128 + tid]);
#pragma unroll
            for (int s = 0; s < 16; s++) fma2(acc[s], w2, Q2[s * 64 + t * 32 + p]);
        }
        __syncthreads();
    }
#pragma unroll
    for (int s = 0; s < 16; s++) {
        float2 f = upk2(acc[s]);
        A[(size_t)(s * 8 + h) * 1024 + jbase + tid] = f.x + f.y;
    }
}

// ---------------------------------------------------------------------------
// Fused write_memory: scores -> softmax -> y, one block per segment.
// grid 64, 512 threads, dyn smem 48KB (a2 32KB + sc 16KB).
// Phase-3 x re-reads hit L2 (segment touched in phase 1).
// ---------------------------------------------------------------------------
__global__ __launch_bounds__(512, 1) void k_wm(const float* __restrict__ x,
                                               const float* __restrict__ A,
                                               float* __restrict__ Y) {
    extern __shared__ float dsm[];
    float* asm_ = dsm;           // [8][1024]
    float* sc   = dsm + 8192;    // [8][512]
    __shared__ float red[16];
    __shared__ float bval;
    int seg = blockIdx.x;
    int s = seg & 15, b = seg >> 4;
    int tid = threadIdx.x, warp = tid >> 5, lane = tid & 31;

    const float* asrc = A + (size_t)s * 8192;
    for (int i = tid; i < 2048; i += 512)
        ((float4*)asm_)[i] = ((const float4*)asrc)[i];
    __syncthreads();
    const ull* a2 = (const ull*)asm_;   // [h][512]

    // ---- phase 1: scores (warp w handles tokens w*32..w*32+31) ----
    for (int tk = 0; tk < 32; ++tk) {
        int l = warp * 32 + tk;
        const ull* xrow = (const ull*)x + (size_t)(b * 8192 + s * 512 + l) * 512;
        ull acc[8];
#pragma unroll
        for (int h = 0; h < 8; h++) acc[h] = 0ull;
#pragma unroll
        for (int i = 0; i < 16; ++i) {
            int c = lane + 32 * i;
            ull xv = xrow[c];
#pragma unroll
            for (int h = 0; h < 8; h++) fma2(acc[h], xv, a2[h * 512 + c]);
        }
#pragma unroll
        for (int h = 0; h < 8; h++) {
            float2 f = upk2(acc[h]);
            float v = f.x + f.y;
            v += __shfl_xor_sync(0xffffffffu, v, 16);
            v += __shfl_xor_sync(0xffffffffu, v, 8);
            v += __shfl_xor_sync(0xffffffffu, v, 4);
            v += __shfl_xor_sync(0xffffffffu, v, 2);
            v += __shfl_xor_sync(0xffffffffu, v, 1);
            if (lane == 0) sc[h * 512 + l] = v * 0.08838834764831845f;
        }
    }
    __syncthreads();

    // ---- phase 2: softmax over l=512 per h ----
    for (int h = 0; h < 8; ++h) {
        float v = sc[h * 512 + tid];
        float m = v;
#pragma unroll
        for (int o = 16; o; o >>= 1) m = fmaxf(m, __shfl_xor_sync(0xffffffffu, m, o));
        if (lane == 0) red[warp] = m;
        __syncthreads();
        if (tid == 0) {
            float mm = red[0];
#pragma unroll
            for (int k = 1; k < 16; k++) mm = fmaxf(mm, red[k]);
            bval = mm;
        }
        __syncthreads();
        float M = bval;
        float e = __expf(v - M);
        float su = e;
#pragma unroll
        for (int o = 16; o; o >>= 1) su += __shfl_xor_sync(0xffffffffu, su, o);
        if (lane == 0) red[warp] = su;
        __syncthreads();
        if (tid == 0) {
            float sm = 0.f;
#pragma unroll
            for (int k = 0; k < 16; k++) sm += red[k];
            bval = sm;
        }
        __syncthreads();
        sc[h * 512 + tid] = e / bval;
        __syncthreads();
    }

    // ---- phase 3: y[h][c] = sum_l w[h][l] * x[l][c] ----
    int c0 = tid, c1 = tid + 512;
    const float* xb = x + (size_t)(b * 8192 + s * 512) * 1024;
    const ull* w2 = (const ull*)sc;   // [h][256] l-pairs
    ull acc0[8], acc1[8];
#pragma unroll
    for (int h = 0; h < 8; h++) { acc0[h] = 0ull; acc1[h] = 0ull; }
#pragma unroll 4
    for (int lp = 0; lp < 256; ++lp) {
        float xa0 = xb[(size_t)(2 * lp) * 1024 + c0];
        float xa1 = xb[(size_t)(2 * lp + 1) * 1024 + c0];
        float xb0 = xb[(size_t)(2 * lp) * 1024 + c1];
        float xb1 = xb[(size_t)(2 * lp + 1) * 1024 + c1];
        ull xpa = pk2(xa0, xa1), xpb = pk2(xb0, xb1);
#pragma unroll
        for (int h = 0; h < 8; h++) {
            ull wv = w2[h * 256 + lp];
            fma2(acc0[h], xpa, wv);
            fma2(acc1[h], xpb, wv);
        }
    }
#pragma unroll
    for (int h = 0; h < 8; h++) {
        float2 f0 = upk2(acc0[h]), f1 = upk2(acc1[h]);
        Y[(size_t)(seg * 8 + h) * 1024 + c0] = f0.x + f0.y;
        Y[(size_t)(seg * 8 + h) * 1024 + c1] = f1.x + f1.y;
    }
}

// ---------------------------------------------------------------------------
// causal self-attention over S=16 slots, per (b,h). grid 32, 256 threads
// ---------------------------------------------------------------------------
__global__ __launch_bounds__(256) void k_slotattn(const float* __restrict__ QKV,
                                                  float* __restrict__ ATT) {
    int b = blockIdx.x >> 3, h = blockIdx.x & 7;
    __shared__ float qs[16][132], ks[16][132], vs[16][132];
    __shared__ float sc[16][17];
    int tid = threadIdx.x;
    for (int i = tid; i < 2048; i += 256) {
        int r = i >> 7, d = i & 127;
        size_t base = (size_t)(b * 16 + r) * 3072 + h * 128 + d;
        qs[r][d] = QKV[base];
        ks[r][d] = QKV[base + 1024];
        vs[r][d] = QKV[base + 2048];
    }
    __syncthreads();
    {
        int i = tid >> 4, jj = tid & 15;
        float dot = 0.f;
#pragma unroll 8
        for (int d = 0; d < 128; ++d) dot += qs[i][d] * ks[jj][d];
        sc[i][jj] = dot * 0.08838834764831845f;
    }
    __syncthreads();
    if (tid < 16) {
        int r = tid;
        float m = -1e30f;
        for (int j = 0; j <= r; ++j) m = fmaxf(m, sc[r][j]);
        float sum = 0.f;
        for (int j = 0; j < 16; ++j) {
            float e = (j <= r) ? __expf(sc[r][j] - m) : 0.f;
            sc[r][j] = e; sum += e;
        }
        float inv = 1.0f / sum;
        for (int j = 0; j < 16; ++j) sc[r][j] *= inv;
    }
    __syncthreads();
    {
        int d = tid & 127;
        int ibase = tid >> 7;
#pragma unroll
        for (int r = 0; r < 8; ++r) {
            int i = ibase + 2 * r;
            float o = 0.f;
#pragma unroll
            for (int j = 0; j < 16; ++j) o += sc[i][j] * vs[j][d];
            ATT[(size_t)(b * 16 + i) * 1024 + h * 128 + d] = o;
        }
    }
}

// ---------------------------------------------------------------------------
// read_memory fused: per token, qk[s]=x·kk[b,s]/32, masked softmax over s,
// out = sum_s w[s]*vr[b,s]. kk & vr in 128KB dyn smem.
// grid (32 chunks, 4 b), 256 threads
// ---------------------------------------------------------------------------
__global__ __launch_bounds__(256, 1) void k_read(const float* __restrict__ x,
                                                 const float* __restrict__ KK,
                                                 const float* __restrict__ VR,
                                                 float* __restrict__ out) {
    extern __shared__ float sm[];
    int b = blockIdx.y, chunk = blockIdx.x;
    const float* kksrc = KK + (size_t)b * 16384;
    const float* vrsrc = VR + (size_t)b * 16384;
    for (int i = threadIdx.x; i < 16384; i += 256) {
        sm[i] = kksrc[i];
        sm[16384 + i] = vrsrc[i];
    }
    __syncthreads();
    const ull* kk2 = (const ull*)sm;              // [s][512]
    const ull* vr2 = (const ull*)(sm + 16384);
    int warp = threadIdx.x >> 5, lane = threadIdx.x & 31;
    int tbase = chunk * 256 + warp * 32;

    for (int p = 0; p < 16; ++p) {
        int t0 = tbase + 2 * p;
        int seg = t0 >> 9;
        const ull* xa = (const ull*)x + (size_t)(b * 8192 + t0) * 512;
        const ull* xb = xa + 512;
        ull acca[16], accb[16];
#pragma unroll
        for (int s = 0; s < 16; s++) { acca[s] = 0ull; accb[s] = 0ull; }
#pragma unroll
        for (int i = 0; i < 16; ++i) {
            int c = lane + 32 * i;
            ull va = xa[c], vb = xb[c];
#pragma unroll
            for (int s = 0; s < 16; s++) {
                ull kv = kk2[s * 512 + c];
                fma2(acca[s], va, kv);
                fma2(accb[s], vb, kv);
            }
        }
        float qa[16], qb[16];
#pragma unroll
        for (int s = 0; s < 16; s++) {
            float2 fa = upk2(acca[s]);
            float va = fa.x + fa.y;
            va += __shfl_xor_sync(0xffffffffu, va, 16);
            va += __shfl_xor_sync(0xffffffffu, va, 8);
            va += __shfl_xor_sync(0xffffffffu, va, 4);
            va += __shfl_xor_sync(0xffffffffu, va, 2);
            va += __shfl_xor_sync(0xffffffffu, va, 1);
            qa[s] = va * 0.03125f;
            float2 fb = upk2(accb[s]);
            float vb = fb.x + fb.y;
            vb += __shfl_xor_sync(0xffffffffu, vb, 16);
            vb += __shfl_xor_sync(0xffffffffu, vb, 8);
            vb += __shfl_xor_sync(0xffffffffu, vb, 4);
            vb += __shfl_xor_sync(0xffffffffu, vb, 2);
            vb += __shfl_xor_sync(0xffffffffu, vb, 1);
            qb[s] = vb * 0.03125f;
        }
        float ma = -1e30f, mb = -1e30f;
#pragma unroll
        for (int s = 0; s < 16; s++) {
            if (s >= seg) { ma = fmaxf(ma, qa[s]); mb = fmaxf(mb, qb[s]); }
        }
        float sa = 0.f, sb = 0.f;
#pragma unroll
        for (int s = 0; s < 16; s++) {
            float ea = (s >= seg) ? __expf(qa[s] - ma) : 0.f;
            float eb = (s >= seg) ? __expf(qb[s] - mb) : 0.f;
            qa[s] = ea; qb[s] = eb; sa += ea; sb += eb;
        }
        float ia = 1.0f / sa, ib = 1.0f / sb;
        ull wa[16], wb[16];
#pragma unroll
        for (int s = 0; s < 16; s++) {
            float a = qa[s] * ia, c = qb[s] * ib;
            wa[s] = pk2(a, a);
            wb[s] = pk2(c, c);
        }
        ull* oa = (ull*)out + (size_t)(b * 8192 + t0) * 512;
        ull* ob = oa + 512;
#pragma unroll
        for (int i = 0; i < 16; ++i) {
            int c = lane + 32 * i;
            ull accoa = 0ull, accob = 0ull;
#pragma unroll
            for (int s = 0; s < 16; s++) {
                ull v = vr2[s * 512 + c];
                fma2(accoa, wa[s], v);
                fma2(accob, wb[s], v);
            }
            oa[c] = accoa;
            ob[c] = accob;
        }
    }
}

// ---------------------------------------------------------------------------
extern "C" void kernel_launch(void* const* d_in, const int* in_sizes, int n_in,
                              void* d_out, int out_size) {
    const float* x     = (const float*)d_in[0];
    const float* slots = (const float*)d_in[1];
    const float* Wrq   = (const float*)d_in[2];
    const float* Wrk   = (const float*)d_in[3];
    const float* Wrv   = (const float*)d_in[4];
    const float* Wwq   = (const float*)d_in[5];
    const float* Wwk   = (const float*)d_in[6];
    const float* Wwv   = (const float*)d_in[7];
    const float* Wqkv  = (const float*)d_in[8];
    const float* Wproj = (const float*)d_in[9];
    float* out    = (float*)d_out;
    float* outmem = out + OUT_ELEMS;

    float* scr = nullptr;
    cudaGetSymbolAddress((void**)&scr, g_scratch);

    cudaFuncSetAttribute(k_tgemm, cudaFuncAttributeMaxDynamicSharedMemorySize, 65536);
    cudaFuncSetAttribute(k_wm, cudaFuncAttributeMaxDynamicSharedMemorySize, 49152);
    cudaFuncSetAttribute(k_read, cudaFuncAttributeMaxDynamicSharedMemorySize, 131072);

    float* NS   = scr + OFF_NS;
    float* Q    = scr + OFF_Q;
    float* A    = scr + OFF_A;
    float* WWKT = scr + OFF_WWKT;
    float* WRQT = scr + OFF_WRQT;
    float* Y    = scr + OFF_Y;
    float* MEM0 = scr + OFF_MEM0;
    float* QKV  = scr + OFF_QKV;
    float* ATT  = scr + OFF_ATT;
    float* PROJ = scr + OFF_PROJ;
    float* MEMN = scr + OFF_MEMN;
    float* KR   = scr + OFF_KR;
    float* VR   = scr + OFF_VR;
    float* KK   = scr + OFF_KK;

    // transposes (Wwk, Wrq)
    k_transpose<<<dim3(32, 32), dim3(32, 8)>>>(Wwk, WWKT);
    k_transpose<<<dim3(32, 32), dim3(32, 8)>>>(Wrq, WRQT);

    // ---- write_memory ----
    k_rownorm<<<16, 256>>>(slots, NS, nullptr);
    k_tgemm<<<dim3(8, 2), 128, 65536>>>(NS, Wwq, Q, 1024, 1, 0);
    k_a2<<<dim3(8, 8), 128>>>(WWKT, Q, A);
    k_wm<<<64, 512, 49152>>>(x, A, Y);
    k_tgemm<<<dim3(8, 8), 128, 65536>>>(Y, Wwv, MEM0, 1024, 8, 1);

    // ---- write_attn ----
    k_tgemm<<<dim3(24, 8), 128, 65536>>>(MEM0, Wqkv, QKV, 3072, 1, 0);
    k_slotattn<<<32, 256>>>(QKV, ATT);
    k_tgemm<<<dim3(8, 8), 128, 65536>>>(ATT, Wproj, PROJ, 1024, 1, 0);
    k_rownorm<<<64, 256>>>(PROJ, MEMN, outmem);

    // ---- read_memory ----
    k_tgemm<<<dim3(8, 8), 128, 65536>>>(MEMN, Wrk, KR, 1024, 1, 0);
    k_tgemm<<<dim3(8, 8), 128, 65536>>>(MEMN, Wrv, VR, 1024, 1, 0);
    k_tgemm<<<dim3(8, 8), 128, 65536>>>(KR, WRQT, KK, 1024, 1, 0);
    k_read<<<dim3(32, 4), 256, 131072>>>(x, KK, VR, out);

    (void)in_sizes; (void)n_in; (void)out_size;
}